// round 5
// baseline (speedup 1.0000x reference)
#include <cuda_runtime.h>
#include <cuda_bf16.h>
#include <math.h>
#include <stdint.h>

#define DIMV   768
#define NHEAD  12
#define HDIMV  64
#define MLPD   3072
#define DEPTH  12
#define BATCH  16
#define SEQ    512
#define MROWS  (BATCH * SEQ)   // 8192

// ---------------------------------------------------------------------------
// Static device scratch (allocation-free contract)
// ---------------------------------------------------------------------------
__device__ __align__(256) __nv_bfloat16 g_lnh[MROWS * DIMV];
__device__ __align__(256) __nv_bfloat16 g_lnl[MROWS * DIMV];
__device__ __align__(256) float         g_q  [MROWS * DIMV];
__device__ __align__(256) float         g_k  [MROWS * DIMV];
__device__ __align__(256) float         g_v  [MROWS * DIMV];
__device__ __align__(256) __nv_bfloat16 g_hh [(size_t)MROWS * MLPD];
__device__ __align__(256) __nv_bfloat16 g_hl [(size_t)MROWS * MLPD];
// transposed + split weights: Wt[N,K]
__device__ __align__(256) __nv_bfloat16 g_wqh[DIMV * DIMV], g_wql[DIMV * DIMV];
__device__ __align__(256) __nv_bfloat16 g_wkh[DIMV * DIMV], g_wkl[DIMV * DIMV];
__device__ __align__(256) __nv_bfloat16 g_wvh[DIMV * DIMV], g_wvl[DIMV * DIMV];
__device__ __align__(256) __nv_bfloat16 g_w1h[DIMV * MLPD], g_w1l[DIMV * MLPD];
__device__ __align__(256) __nv_bfloat16 g_w2h[DIMV * MLPD], g_w2l[DIMV * MLPD];

// ---------------------------------------------------------------------------
// Helpers
// ---------------------------------------------------------------------------
__device__ __forceinline__ void split2(float v, __nv_bfloat16& h, __nv_bfloat16& l) {
    h = __float2bfloat16(v);
    l = __float2bfloat16(v - __bfloat162float(h));
}

#define LDM_X4(r0, r1, r2, r3, addr)                                        \
    asm volatile("ldmatrix.sync.aligned.m8n8.x4.shared.b16 {%0,%1,%2,%3}, [%4];" \
        : "=r"(r0), "=r"(r1), "=r"(r2), "=r"(r3) : "r"(addr))

#define MMA16816(d, a0, a1, a2, a3, b0, b1)                                 \
    asm volatile("mma.sync.aligned.m16n8k16.row.col.f32.bf16.bf16.f32 "     \
        "{%0,%1,%2,%3}, {%4,%5,%6,%7}, {%8,%9}, {%0,%1,%2,%3};"             \
        : "+f"((d)[0]), "+f"((d)[1]), "+f"((d)[2]), "+f"((d)[3])            \
        : "r"(a0), "r"(a1), "r"(a2), "r"(a3), "r"(b0), "r"(b1))

#define CP_ASYNC16(smem_u32, gptr)                                          \
    asm volatile("cp.async.cg.shared.global [%0], [%1], 16;"                \
        :: "r"(smem_u32), "l"(gptr))
#define CP_COMMIT()  asm volatile("cp.async.commit_group;" ::: "memory")
#define CP_WAIT1()   asm volatile("cp.async.wait_group 1;" ::: "memory")
#define CP_WAIT0()   asm volatile("cp.async.wait_group 0;" ::: "memory")

// ---------------------------------------------------------------------------
// LayerNorm -> bf16 hi/lo split. One block per row, 256 threads.
// ---------------------------------------------------------------------------
__global__ __launch_bounds__(256) void ln_split_kernel(
    const float* __restrict__ x, const float* __restrict__ w,
    const float* __restrict__ b,
    __nv_bfloat16* __restrict__ yh, __nv_bfloat16* __restrict__ yl)
{
    int row = blockIdx.x;
    const float* xr = x + (size_t)row * DIMV;

    float v[3];
    float s = 0.f, ss = 0.f;
#pragma unroll
    for (int i = 0; i < 3; i++) {
        v[i] = xr[threadIdx.x + i * 256];
        s += v[i]; ss += v[i] * v[i];
    }
#pragma unroll
    for (int off = 16; off > 0; off >>= 1) {
        s  += __shfl_xor_sync(0xffffffffu, s,  off);
        ss += __shfl_xor_sync(0xffffffffu, ss, off);
    }
    __shared__ float r0s[8], r1s[8], stat[2];
    int wid = threadIdx.x >> 5, lid = threadIdx.x & 31;
    if (lid == 0) { r0s[wid] = s; r1s[wid] = ss; }
    __syncthreads();
    if (threadIdx.x == 0) {
        float ts = 0.f, tss = 0.f;
#pragma unroll
        for (int i = 0; i < 8; i++) { ts += r0s[i]; tss += r1s[i]; }
        float mu = ts / DIMV;
        stat[0] = mu;
        stat[1] = rsqrtf(tss / DIMV - mu * mu + 1e-5f);
    }
    __syncthreads();
    float mu = stat[0], rstd = stat[1];
#pragma unroll
    for (int i = 0; i < 3; i++) {
        int c = threadIdx.x + i * 256;
        float y = (v[i] - mu) * rstd * w[c] + b[c];
        __nv_bfloat16 h, l;
        split2(y, h, l);
        yh[(size_t)row * DIMV + c] = h;
        yl[(size_t)row * DIMV + c] = l;
    }
}

// ---------------------------------------------------------------------------
// Weight prep: out[N,K] (hi/lo bf16) = transpose(in[K,N]) with split.
// block (32,8), grid (N/32, K/32)
// ---------------------------------------------------------------------------
__global__ __launch_bounds__(256) void wprep_kernel(
    const float* __restrict__ in, __nv_bfloat16* __restrict__ oh,
    __nv_bfloat16* __restrict__ ol, int K, int N)
{
    __shared__ float t[32][33];
    int n0 = blockIdx.x * 32, k0 = blockIdx.y * 32;
#pragma unroll
    for (int i = 0; i < 4; i++) {
        int k = k0 + threadIdx.y + i * 8;
        t[threadIdx.y + i * 8][threadIdx.x] = in[(size_t)k * N + n0 + threadIdx.x];
    }
    __syncthreads();
#pragma unroll
    for (int i = 0; i < 4; i++) {
        int n = n0 + threadIdx.y + i * 8;
        float v = t[threadIdx.x][threadIdx.y + i * 8];
        __nv_bfloat16 h, l;
        split2(v, h, l);
        oh[(size_t)n * K + k0 + threadIdx.x] = h;
        ol[(size_t)n * K + k0 + threadIdx.x] = l;
    }
}

// ---------------------------------------------------------------------------
// HMMA GEMM (bf16x3 split), cp.async double-buffered.
// C[M,N] = A[M,K] @ Wt[N,K]^T + bias
// Block tile 128x64, BK=64, 256 threads = 8 warps (4m x 2n), warp tile 32x32.
// EPI 0: C fp32 = acc+bias
// EPI 1: gelu(acc+bias) -> bf16 hi/lo
// EPI 2: C fp32 += acc+bias (residual)
// Per-buffer layout (halves, 72-half padded rows):
//   Ah[128][72] @0, Al @9216, Bh[64][72] @18432, Bl @23040 -> 27648 halves
// Two buffers: 2 * 55296 B = 110592 B dynamic smem.
// ---------------------------------------------------------------------------
#define GSM_AH 0
#define GSM_AL 9216
#define GSM_BH 18432
#define GSM_BL 23040
#define BUF_HALVES 27648
#define GEMM_SMEM (2 * BUF_HALVES * 2)

template <int EPI>
__global__ __launch_bounds__(256, 2) void gemm_hmma(
    const __nv_bfloat16* __restrict__ Ahg, const __nv_bfloat16* __restrict__ Alg,
    const __nv_bfloat16* __restrict__ Bhg, const __nv_bfloat16* __restrict__ Blg,
    const float* __restrict__ bias, float* __restrict__ C,
    __nv_bfloat16* __restrict__ Oh, __nv_bfloat16* __restrict__ Ol,
    int N, int K)
{
    extern __shared__ __nv_bfloat16 sm[];

    const int tid  = threadIdx.x;
    const int warp = tid >> 5, lane = tid & 31;
    const int bm = blockIdx.y * 128, bn = blockIdx.x * 64;
    const int wm = (warp >> 1) * 32;
    const int wn = (warp & 1) * 32;

    float acc[2][4][4];
#pragma unroll
    for (int mt = 0; mt < 2; mt++)
#pragma unroll
        for (int nt = 0; nt < 4; nt++)
#pragma unroll
            for (int i = 0; i < 4; i++) acc[mt][nt][i] = 0.f;

    const uint32_t base = (uint32_t)__cvta_generic_to_shared(sm);

    // cp.async fill mapping: 16B chunks (8 halves).
    // A (hi & lo): 128 rows x 8 chunks = 1024 chunks -> 4 per thread.
    // B (hi & lo): 64 rows x 8 chunks = 512 chunks -> 2 per thread.
    // chunk c: row = c>>3, j = c&7 (j*8 halves within BK=64).

    // ldmatrix addresses
    const uint32_t a_row = wm + (lane & 15);
    const uint32_t a_koff = ((lane >> 4) & 1) * 8;
    const uint32_t b_row = wn + (lane & 7) + ((lane >> 4) & 1) * 8;
    const uint32_t b_koff = ((lane >> 3) & 1) * 8;

    const int nstages = K / 64;

    // ---- fill helper (macro-ish lambda) ----
    auto fill_stage = [&](int buf, int k0) {
        const uint32_t bofs = (uint32_t)buf * BUF_HALVES;
#pragma unroll
        for (int i = 0; i < 4; i++) {
            int c = tid + i * 256;
            int r = c >> 3, j = c & 7;
            const __nv_bfloat16* gh = Ahg + (size_t)(bm + r) * K + k0 + j * 8;
            const __nv_bfloat16* gl = Alg + (size_t)(bm + r) * K + k0 + j * 8;
            uint32_t sh = base + (bofs + GSM_AH + r * 72 + j * 8) * 2;
            uint32_t sl = base + (bofs + GSM_AL + r * 72 + j * 8) * 2;
            CP_ASYNC16(sh, gh);
            CP_ASYNC16(sl, gl);
        }
#pragma unroll
        for (int i = 0; i < 2; i++) {
            int c = tid + i * 256;
            int r = c >> 3, j = c & 7;
            const __nv_bfloat16* gh = Bhg + (size_t)(bn + r) * K + k0 + j * 8;
            const __nv_bfloat16* gl = Blg + (size_t)(bn + r) * K + k0 + j * 8;
            uint32_t sh = base + (bofs + GSM_BH + r * 72 + j * 8) * 2;
            uint32_t sl = base + (bofs + GSM_BL + r * 72 + j * 8) * 2;
            CP_ASYNC16(sh, gh);
            CP_ASYNC16(sl, gl);
        }
        CP_COMMIT();
    };

    // prologue
    fill_stage(0, 0);

    for (int s = 0; s < nstages; s++) {
        if (s + 1 < nstages) {
            fill_stage((s + 1) & 1, (s + 1) * 64);
            CP_WAIT1();             // stage s's group is complete
        } else {
            CP_WAIT0();
        }
        __syncthreads();

        const uint32_t bofs = (uint32_t)(s & 1) * BUF_HALVES;
#pragma unroll
        for (int kk = 0; kk < 64; kk += 16) {
            uint32_t afh[2][4], afl[2][4], bfh[2][4], bfl[2][4];
#pragma unroll
            for (int mt = 0; mt < 2; mt++) {
                uint32_t adr = base + (bofs + GSM_AH + (a_row + mt * 16) * 72 + kk + a_koff) * 2;
                LDM_X4(afh[mt][0], afh[mt][1], afh[mt][2], afh[mt][3], adr);
                adr = base + (bofs + GSM_AL + (a_row + mt * 16) * 72 + kk + a_koff) * 2;
                LDM_X4(afl[mt][0], afl[mt][1], afl[mt][2], afl[mt][3], adr);
            }
#pragma unroll
            for (int p = 0; p < 2; p++) {
                uint32_t adr = base + (bofs + GSM_BH + (b_row + p * 16) * 72 + kk + b_koff) * 2;
                LDM_X4(bfh[p][0], bfh[p][1], bfh[p][2], bfh[p][3], adr);
                adr = base + (bofs + GSM_BL + (b_row + p * 16) * 72 + kk + b_koff) * 2;
                LDM_X4(bfl[p][0], bfl[p][1], bfl[p][2], bfl[p][3], adr);
            }
#pragma unroll
            for (int mt = 0; mt < 2; mt++)
#pragma unroll
                for (int nt = 0; nt < 4; nt++) {
                    const int p = nt >> 1, q = (nt & 1) * 2;
                    MMA16816(acc[mt][nt], afh[mt][0], afh[mt][1], afh[mt][2], afh[mt][3],
                             bfh[p][q], bfh[p][q + 1]);
                    MMA16816(acc[mt][nt], afh[mt][0], afh[mt][1], afh[mt][2], afh[mt][3],
                             bfl[p][q], bfl[p][q + 1]);
                    MMA16816(acc[mt][nt], afl[mt][0], afl[mt][1], afl[mt][2], afl[mt][3],
                             bfh[p][q], bfh[p][q + 1]);
                }
        }
        __syncthreads();
    }

    // ---- epilogue ----
    const int erow = lane >> 2;
    const int ecol = 2 * (lane & 3);
#pragma unroll
    for (int mt = 0; mt < 2; mt++)
#pragma unroll
        for (int nt = 0; nt < 4; nt++) {
            int row0 = bm + wm + mt * 16 + erow;
            int col  = bn + wn + nt * 8 + ecol;
            float b0 = bias[col], b1 = bias[col + 1];
            float v00 = acc[mt][nt][0] + b0, v01 = acc[mt][nt][1] + b1;
            float v10 = acc[mt][nt][2] + b0, v11 = acc[mt][nt][3] + b1;
            if (EPI == 1) {
                v00 = 0.5f * v00 * (1.0f + erff(v00 * 0.70710678118654752f));
                v01 = 0.5f * v01 * (1.0f + erff(v01 * 0.70710678118654752f));
                v10 = 0.5f * v10 * (1.0f + erff(v10 * 0.70710678118654752f));
                v11 = 0.5f * v11 * (1.0f + erff(v11 * 0.70710678118654752f));
                __nv_bfloat16 h0, l0, h1, l1;
                split2(v00, h0, l0); split2(v01, h1, l1);
                *(__nv_bfloat162*)(Oh + (size_t)row0 * N + col) = __nv_bfloat162(h0, h1);
                *(__nv_bfloat162*)(Ol + (size_t)row0 * N + col) = __nv_bfloat162(l0, l1);
                split2(v10, h0, l0); split2(v11, h1, l1);
                *(__nv_bfloat162*)(Oh + (size_t)(row0 + 8) * N + col) = __nv_bfloat162(h0, h1);
                *(__nv_bfloat162*)(Ol + (size_t)(row0 + 8) * N + col) = __nv_bfloat162(l0, l1);
            } else {
                float2* p0 = (float2*)(C + (size_t)row0 * N + col);
                float2* p1 = (float2*)(C + (size_t)(row0 + 8) * N + col);
                if (EPI == 2) {
                    float2 c0 = *p0, c1 = *p1;
                    v00 += c0.x; v01 += c0.y; v10 += c1.x; v11 += c1.y;
                }
                *p0 = make_float2(v00, v01);
                *p1 = make_float2(v10, v11);
            }
        }
}

// ---------------------------------------------------------------------------
// Flash-style attention + fused residual add (fp32 SIMT).
// Grid: (qtile=8, head=12, batch=16), 256 threads.
// ---------------------------------------------------------------------------
__global__ __launch_bounds__(256) void attn_kernel(
    const float* __restrict__ Q, const float* __restrict__ Kp,
    const float* __restrict__ V, float* __restrict__ X)
{
    __shared__ float Qs[64][68];
    __shared__ float Ks[32][68];
    __shared__ float Vs[32][68];
    __shared__ float Ps[64][36];

    int tid = threadIdx.x;
    int qt = blockIdx.x, h = blockIdx.y, b = blockIdx.z;
    int q0 = b * SEQ + qt * 64;
    int hc = h * HDIMV;

#pragma unroll
    for (int j = 0; j < 4; j++) {
        int f = tid + j * 256;
        int r = f >> 4, c = (f & 15) * 4;
        *(float4*)&Qs[r][c] = *(const float4*)(Q + (size_t)(q0 + r) * DIMV + hc + c);
    }

    int ty = tid >> 4, tx = tid & 15;
    float m_run[4], l_run[4], o[4][4];
#pragma unroll
    for (int r = 0; r < 4; r++) {
        m_run[r] = -1e30f; l_run[r] = 0.f;
#pragma unroll
        for (int c = 0; c < 4; c++) o[r][c] = 0.f;
    }

    for (int kt = 0; kt < 16; kt++) {
        int k0 = b * SEQ + kt * 32;
#pragma unroll
        for (int j = 0; j < 2; j++) {
            int f = tid + j * 256;
            int r = f >> 4, c = (f & 15) * 4;
            *(float4*)&Ks[r][c] = *(const float4*)(Kp + (size_t)(k0 + r) * DIMV + hc + c);
            *(float4*)&Vs[r][c] = *(const float4*)(V  + (size_t)(k0 + r) * DIMV + hc + c);
        }
        __syncthreads();

        float s[4][2];
#pragma unroll
        for (int r = 0; r < 4; r++) { s[r][0] = 0.f; s[r][1] = 0.f; }
#pragma unroll
        for (int d = 0; d < 64; d += 4) {
            float4 qv[4], kv[2];
#pragma unroll
            for (int r = 0; r < 4; r++) qv[r] = *(const float4*)&Qs[ty * 4 + r][d];
#pragma unroll
            for (int c = 0; c < 2; c++) kv[c] = *(const float4*)&Ks[tx * 2 + c][d];
#pragma unroll
            for (int r = 0; r < 4; r++)
#pragma unroll
                for (int c = 0; c < 2; c++)
                    s[r][c] += qv[r].x * kv[c].x + qv[r].y * kv[c].y +
                               qv[r].z * kv[c].z + qv[r].w * kv[c].w;
        }

#pragma unroll
        for (int r = 0; r < 4; r++) {
            s[r][0] *= 0.125f;
            s[r][1] *= 0.125f;
            float mt = fmaxf(s[r][0], s[r][1]);
#pragma unroll
            for (int off = 1; off < 16; off <<= 1)
                mt = fmaxf(mt, __shfl_xor_sync(0xffffffffu, mt, off));
            float m_new = fmaxf(m_run[r], mt);
            float alpha = __expf(m_run[r] - m_new);
            float p0 = __expf(s[r][0] - m_new);
            float p1 = __expf(s[r][1] - m_new);
            float rs = p0 + p1;
#pragma unroll
            for (int off = 1; off < 16; off <<= 1)
                rs += __shfl_xor_sync(0xffffffffu, rs, off);
            l_run[r] = l_run[r] * alpha + rs;
            m_run[r] = m_new;
            Ps[ty * 4 + r][tx * 2 + 0] = p0;
            Ps[ty * 4 + r][tx * 2 + 1] = p1;
#pragma unroll
            for (int c = 0; c < 4; c++) o[r][c] *= alpha;
        }
        __syncthreads();

#pragma unroll
        for (int kk = 0; kk < 32; kk++) {
            float4 vv = *(const float4*)&Vs[kk][tx * 4];
#pragma unroll
            for (int r = 0; r < 4; r++) {
                float p = Ps[ty * 4 + r][kk];
                o[r][0] += p * vv.x;
                o[r][1] += p * vv.y;
                o[r][2] += p * vv.z;
                o[r][3] += p * vv.w;
            }
        }
        __syncthreads();
    }

#pragma unroll
    for (int r = 0; r < 4; r++) {
        float inv = 1.0f / l_run[r];
        float* xp = X + (size_t)(q0 + ty * 4 + r) * DIMV + hc + tx * 4;
#pragma unroll
        for (int c = 0; c < 4; c++) xp[c] += o[r][c] * inv;
    }
}

// ---------------------------------------------------------------------------
// Launch
// ---------------------------------------------------------------------------
extern "C" void kernel_launch(void* const* d_in, const int* in_sizes, int n_in,
                              void* d_out, int out_size)
{
    const float* x_in = (const float*)d_in[0];
    const float* ln_w = (const float*)d_in[1];
    const float* ln_b = (const float*)d_in[2];
    const float* wq   = (const float*)d_in[3];
    const float* bq   = (const float*)d_in[4];
    const float* wk   = (const float*)d_in[5];
    const float* bk   = (const float*)d_in[6];
    const float* wv   = (const float*)d_in[7];
    const float* bv   = (const float*)d_in[8];
    const float* w1   = (const float*)d_in[9];
    const float* b1   = (const float*)d_in[10];
    const float* w2   = (const float*)d_in[11];
    const float* b2   = (const float*)d_in[12];

    float* X = (float*)d_out;

    __nv_bfloat16 *lnh, *lnl, *hh, *hl;
    __nv_bfloat16 *wqh, *wql, *wkh, *wkl, *wvh, *wvl, *w1h, *w1l, *w2h, *w2l;
    float *q, *k, *v;
    cudaGetSymbolAddress((void**)&lnh, g_lnh);
    cudaGetSymbolAddress((void**)&lnl, g_lnl);
    cudaGetSymbolAddress((void**)&hh,  g_hh);
    cudaGetSymbolAddress((void**)&hl,  g_hl);
    cudaGetSymbolAddress((void**)&q,   g_q);
    cudaGetSymbolAddress((void**)&k,   g_k);
    cudaGetSymbolAddress((void**)&v,   g_v);
    cudaGetSymbolAddress((void**)&wqh, g_wqh);
    cudaGetSymbolAddress((void**)&wql, g_wql);
    cudaGetSymbolAddress((void**)&wkh, g_wkh);
    cudaGetSymbolAddress((void**)&wkl, g_wkl);
    cudaGetSymbolAddress((void**)&wvh, g_wvh);
    cudaGetSymbolAddress((void**)&wvl, g_wvl);
    cudaGetSymbolAddress((void**)&w1h, g_w1h);
    cudaGetSymbolAddress((void**)&w1l, g_w1l);
    cudaGetSymbolAddress((void**)&w2h, g_w2h);
    cudaGetSymbolAddress((void**)&w2l, g_w2l);

    cudaFuncSetAttribute(gemm_hmma<0>, cudaFuncAttributeMaxDynamicSharedMemorySize, GEMM_SMEM);
    cudaFuncSetAttribute(gemm_hmma<1>, cudaFuncAttributeMaxDynamicSharedMemorySize, GEMM_SMEM);
    cudaFuncSetAttribute(gemm_hmma<2>, cudaFuncAttributeMaxDynamicSharedMemorySize, GEMM_SMEM);

    // residual stream <- input
    cudaMemcpyAsync(X, x_in, sizeof(float) * (size_t)MROWS * DIMV,
                    cudaMemcpyDeviceToDevice, 0);

    // weight prep (once per launch)
    dim3 tb(32, 8);
    wprep_kernel<<<dim3(DIMV / 32, DIMV / 32), tb>>>(wq, wqh, wql, DIMV, DIMV);
    wprep_kernel<<<dim3(DIMV / 32, DIMV / 32), tb>>>(wk, wkh, wkl, DIMV, DIMV);
    wprep_kernel<<<dim3(DIMV / 32, DIMV / 32), tb>>>(wv, wvh, wvl, DIMV, DIMV);
    wprep_kernel<<<dim3(MLPD / 32, DIMV / 32), tb>>>(w1, w1h, w1l, DIMV, MLPD);
    wprep_kernel<<<dim3(DIMV / 32, MLPD / 32), tb>>>(w2, w2h, w2l, MLPD, DIMV);

    dim3 gQKV(DIMV / 64, MROWS / 128);    // (12, 64)
    dim3 gMLP1(MLPD / 64, MROWS / 128);   // (48, 64)
    dim3 gAttn(SEQ / 64, NHEAD, BATCH);

    for (int layer = 0; layer < DEPTH; layer++) {
        ln_split_kernel<<<MROWS, 256>>>(X, ln_w, ln_b, lnh, lnl);

        gemm_hmma<0><<<gQKV, 256, GEMM_SMEM>>>(lnh, lnl, wqh, wql, bq, q, nullptr, nullptr, DIMV, DIMV);
        gemm_hmma<0><<<gQKV, 256, GEMM_SMEM>>>(lnh, lnl, wkh, wkl, bk, k, nullptr, nullptr, DIMV, DIMV);
        gemm_hmma<0><<<gQKV, 256, GEMM_SMEM>>>(lnh, lnl, wvh, wvl, bv, v, nullptr, nullptr, DIMV, DIMV);

        attn_kernel<<<gAttn, 256>>>(q, k, v, X);

        ln_split_kernel<<<MROWS, 256>>>(X, ln_w, ln_b, lnh, lnl);

        gemm_hmma<1><<<gMLP1, 256, GEMM_SMEM>>>(lnh, lnl, w1h, w1l, b1, nullptr, hh, hl, MLPD, DIMV);
        gemm_hmma<2><<<gQKV, 256, GEMM_SMEM>>>(hh, hl, w2h, w2l, b2, X, nullptr, nullptr, DIMV, MLPD);
    }
}

// round 6
// speedup vs baseline: 1.1907x; 1.1907x over previous
#include <cuda_runtime.h>
#include <cuda_bf16.h>
#include <math.h>
#include <stdint.h>

#define DIMV   768
#define NHEAD  12
#define HDIMV  64
#define MLPD   3072
#define DEPTH  12
#define BATCH  16
#define SEQ    512
#define MROWS  (BATCH * SEQ)   // 8192

// ---------------------------------------------------------------------------
// Static device scratch (allocation-free contract)
// ---------------------------------------------------------------------------
__device__ __align__(256) __nv_bfloat16 g_lnh[MROWS * DIMV];
__device__ __align__(256) __nv_bfloat16 g_lnl[MROWS * DIMV];
__device__ __align__(256) float         g_q  [MROWS * DIMV];
__device__ __align__(256) float         g_k  [MROWS * DIMV];
__device__ __align__(256) float         g_v  [MROWS * DIMV];
__device__ __align__(256) __nv_bfloat16 g_hh [(size_t)MROWS * MLPD];
__device__ __align__(256) __nv_bfloat16 g_hl [(size_t)MROWS * MLPD];
// transposed + split weights: Wt[N,K]
__device__ __align__(256) __nv_bfloat16 g_wqh[DIMV * DIMV], g_wql[DIMV * DIMV];
__device__ __align__(256) __nv_bfloat16 g_wkh[DIMV * DIMV], g_wkl[DIMV * DIMV];
__device__ __align__(256) __nv_bfloat16 g_wvh[DIMV * DIMV], g_wvl[DIMV * DIMV];
__device__ __align__(256) __nv_bfloat16 g_w1h[DIMV * MLPD], g_w1l[DIMV * MLPD];
__device__ __align__(256) __nv_bfloat16 g_w2h[DIMV * MLPD], g_w2l[DIMV * MLPD];

// ---------------------------------------------------------------------------
// Helpers
// ---------------------------------------------------------------------------
__device__ __forceinline__ void split2(float v, __nv_bfloat16& h, __nv_bfloat16& l) {
    h = __float2bfloat16(v);
    l = __float2bfloat16(v - __bfloat162float(h));
}

__device__ __forceinline__ void pack_split(float a, float b, uint32_t& hi, uint32_t& lo) {
    __nv_bfloat16 ah, al, bh, bl;
    split2(a, ah, al);
    split2(b, bh, bl);
    __nv_bfloat162 hv(ah, bh), lv(al, bl);
    hi = *reinterpret_cast<uint32_t*>(&hv);
    lo = *reinterpret_cast<uint32_t*>(&lv);
}

#define LDM_X4(r0, r1, r2, r3, addr)                                        \
    asm volatile("ldmatrix.sync.aligned.m8n8.x4.shared.b16 {%0,%1,%2,%3}, [%4];" \
        : "=r"(r0), "=r"(r1), "=r"(r2), "=r"(r3) : "r"(addr))

#define MMA16816(d, a0, a1, a2, a3, b0, b1)                                 \
    asm volatile("mma.sync.aligned.m16n8k16.row.col.f32.bf16.bf16.f32 "     \
        "{%0,%1,%2,%3}, {%4,%5,%6,%7}, {%8,%9}, {%0,%1,%2,%3};"             \
        : "+f"((d)[0]), "+f"((d)[1]), "+f"((d)[2]), "+f"((d)[3])            \
        : "r"(a0), "r"(a1), "r"(a2), "r"(a3), "r"(b0), "r"(b1))

#define CP_ASYNC16(smem_u32, gptr)                                          \
    asm volatile("cp.async.cg.shared.global [%0], [%1], 16;"                \
        :: "r"(smem_u32), "l"(gptr))
#define CP_COMMIT()  asm volatile("cp.async.commit_group;" ::: "memory")
#define CP_WAIT1()   asm volatile("cp.async.wait_group 1;" ::: "memory")
#define CP_WAIT0()   asm volatile("cp.async.wait_group 0;" ::: "memory")

// ---------------------------------------------------------------------------
// LayerNorm -> bf16 hi/lo split. One block per row, 256 threads.
// ---------------------------------------------------------------------------
__global__ __launch_bounds__(256) void ln_split_kernel(
    const float* __restrict__ x, const float* __restrict__ w,
    const float* __restrict__ b,
    __nv_bfloat16* __restrict__ yh, __nv_bfloat16* __restrict__ yl)
{
    int row = blockIdx.x;
    const float* xr = x + (size_t)row * DIMV;

    float v[3];
    float s = 0.f, ss = 0.f;
#pragma unroll
    for (int i = 0; i < 3; i++) {
        v[i] = xr[threadIdx.x + i * 256];
        s += v[i]; ss += v[i] * v[i];
    }
#pragma unroll
    for (int off = 16; off > 0; off >>= 1) {
        s  += __shfl_xor_sync(0xffffffffu, s,  off);
        ss += __shfl_xor_sync(0xffffffffu, ss, off);
    }
    __shared__ float r0s[8], r1s[8], stat[2];
    int wid = threadIdx.x >> 5, lid = threadIdx.x & 31;
    if (lid == 0) { r0s[wid] = s; r1s[wid] = ss; }
    __syncthreads();
    if (threadIdx.x == 0) {
        float ts = 0.f, tss = 0.f;
#pragma unroll
        for (int i = 0; i < 8; i++) { ts += r0s[i]; tss += r1s[i]; }
        float mu = ts / DIMV;
        stat[0] = mu;
        stat[1] = rsqrtf(tss / DIMV - mu * mu + 1e-5f);
    }
    __syncthreads();
    float mu = stat[0], rstd = stat[1];
#pragma unroll
    for (int i = 0; i < 3; i++) {
        int c = threadIdx.x + i * 256;
        float y = (v[i] - mu) * rstd * w[c] + b[c];
        __nv_bfloat16 h, l;
        split2(y, h, l);
        yh[(size_t)row * DIMV + c] = h;
        yl[(size_t)row * DIMV + c] = l;
    }
}

// ---------------------------------------------------------------------------
// Fused weight prep (single launch): transpose + hi/lo split for all 5 weights.
// grid (96, 96, 5), block (32,8). Out-of-range tiles exit early.
// ---------------------------------------------------------------------------
__global__ __launch_bounds__(256) void wprep_all(
    const float* __restrict__ wq, const float* __restrict__ wk,
    const float* __restrict__ wv, const float* __restrict__ w1,
    const float* __restrict__ w2,
    __nv_bfloat16* wqh, __nv_bfloat16* wql,
    __nv_bfloat16* wkh, __nv_bfloat16* wkl,
    __nv_bfloat16* wvh, __nv_bfloat16* wvl,
    __nv_bfloat16* w1h, __nv_bfloat16* w1l,
    __nv_bfloat16* w2h, __nv_bfloat16* w2l)
{
    const float* in; __nv_bfloat16 *oh, *ol; int K, N;
    switch (blockIdx.z) {
        case 0: in = wq; oh = wqh; ol = wql; K = DIMV; N = DIMV; break;
        case 1: in = wk; oh = wkh; ol = wkl; K = DIMV; N = DIMV; break;
        case 2: in = wv; oh = wvh; ol = wvl; K = DIMV; N = DIMV; break;
        case 3: in = w1; oh = w1h; ol = w1l; K = DIMV; N = MLPD; break;
        default: in = w2; oh = w2h; ol = w2l; K = MLPD; N = DIMV; break;
    }
    int n0 = blockIdx.x * 32, k0 = blockIdx.y * 32;
    if (n0 >= N || k0 >= K) return;

    __shared__ float t[32][33];
#pragma unroll
    for (int i = 0; i < 4; i++) {
        int k = k0 + threadIdx.y + i * 8;
        t[threadIdx.y + i * 8][threadIdx.x] = in[(size_t)k * N + n0 + threadIdx.x];
    }
    __syncthreads();
#pragma unroll
    for (int i = 0; i < 4; i++) {
        int n = n0 + threadIdx.y + i * 8;
        float v = t[threadIdx.x][threadIdx.y + i * 8];
        __nv_bfloat16 h, l;
        split2(v, h, l);
        oh[(size_t)n * K + k0 + threadIdx.x] = h;
        ol[(size_t)n * K + k0 + threadIdx.x] = l;
    }
}

// ---------------------------------------------------------------------------
// HMMA GEMM (bf16x3 split), cp.async double-buffered. (unchanged; validated)
// ---------------------------------------------------------------------------
#define GSM_AH 0
#define GSM_AL 9216
#define GSM_BH 18432
#define GSM_BL 23040
#define BUF_HALVES 27648
#define GEMM_SMEM (2 * BUF_HALVES * 2)

template <int EPI>
__global__ __launch_bounds__(256, 2) void gemm_hmma(
    const __nv_bfloat16* __restrict__ Ahg, const __nv_bfloat16* __restrict__ Alg,
    const __nv_bfloat16* __restrict__ Bhg, const __nv_bfloat16* __restrict__ Blg,
    const float* __restrict__ bias, float* __restrict__ C,
    __nv_bfloat16* __restrict__ Oh, __nv_bfloat16* __restrict__ Ol,
    int N, int K)
{
    extern __shared__ __nv_bfloat16 sm[];

    const int tid  = threadIdx.x;
    const int warp = tid >> 5, lane = tid & 31;
    const int bm = blockIdx.y * 128, bn = blockIdx.x * 64;
    const int wm = (warp >> 1) * 32;
    const int wn = (warp & 1) * 32;

    float acc[2][4][4];
#pragma unroll
    for (int mt = 0; mt < 2; mt++)
#pragma unroll
        for (int nt = 0; nt < 4; nt++)
#pragma unroll
            for (int i = 0; i < 4; i++) acc[mt][nt][i] = 0.f;

    const uint32_t base = (uint32_t)__cvta_generic_to_shared(sm);

    const uint32_t a_row = wm + (lane & 15);
    const uint32_t a_koff = ((lane >> 4) & 1) * 8;
    const uint32_t b_row = wn + (lane & 7) + ((lane >> 4) & 1) * 8;
    const uint32_t b_koff = ((lane >> 3) & 1) * 8;

    const int nstages = K / 64;

    auto fill_stage = [&](int buf, int k0) {
        const uint32_t bofs = (uint32_t)buf * BUF_HALVES;
#pragma unroll
        for (int i = 0; i < 4; i++) {
            int c = tid + i * 256;
            int r = c >> 3, j = c & 7;
            const __nv_bfloat16* gh = Ahg + (size_t)(bm + r) * K + k0 + j * 8;
            const __nv_bfloat16* gl = Alg + (size_t)(bm + r) * K + k0 + j * 8;
            uint32_t sh = base + (bofs + GSM_AH + r * 72 + j * 8) * 2;
            uint32_t sl = base + (bofs + GSM_AL + r * 72 + j * 8) * 2;
            CP_ASYNC16(sh, gh);
            CP_ASYNC16(sl, gl);
        }
#pragma unroll
        for (int i = 0; i < 2; i++) {
            int c = tid + i * 256;
            int r = c >> 3, j = c & 7;
            const __nv_bfloat16* gh = Bhg + (size_t)(bn + r) * K + k0 + j * 8;
            const __nv_bfloat16* gl = Blg + (size_t)(bn + r) * K + k0 + j * 8;
            uint32_t sh = base + (bofs + GSM_BH + r * 72 + j * 8) * 2;
            uint32_t sl = base + (bofs + GSM_BL + r * 72 + j * 8) * 2;
            CP_ASYNC16(sh, gh);
            CP_ASYNC16(sl, gl);
        }
        CP_COMMIT();
    };

    fill_stage(0, 0);

    for (int s = 0; s < nstages; s++) {
        if (s + 1 < nstages) {
            fill_stage((s + 1) & 1, (s + 1) * 64);
            CP_WAIT1();
        } else {
            CP_WAIT0();
        }
        __syncthreads();

        const uint32_t bofs = (uint32_t)(s & 1) * BUF_HALVES;
#pragma unroll
        for (int kk = 0; kk < 64; kk += 16) {
            uint32_t afh[2][4], afl[2][4], bfh[2][4], bfl[2][4];
#pragma unroll
            for (int mt = 0; mt < 2; mt++) {
                uint32_t adr = base + (bofs + GSM_AH + (a_row + mt * 16) * 72 + kk + a_koff) * 2;
                LDM_X4(afh[mt][0], afh[mt][1], afh[mt][2], afh[mt][3], adr);
                adr = base + (bofs + GSM_AL + (a_row + mt * 16) * 72 + kk + a_koff) * 2;
                LDM_X4(afl[mt][0], afl[mt][1], afl[mt][2], afl[mt][3], adr);
            }
#pragma unroll
            for (int p = 0; p < 2; p++) {
                uint32_t adr = base + (bofs + GSM_BH + (b_row + p * 16) * 72 + kk + b_koff) * 2;
                LDM_X4(bfh[p][0], bfh[p][1], bfh[p][2], bfh[p][3], adr);
                adr = base + (bofs + GSM_BL + (b_row + p * 16) * 72 + kk + b_koff) * 2;
                LDM_X4(bfl[p][0], bfl[p][1], bfl[p][2], bfl[p][3], adr);
            }
#pragma unroll
            for (int mt = 0; mt < 2; mt++)
#pragma unroll
                for (int nt = 0; nt < 4; nt++) {
                    const int p = nt >> 1, q = (nt & 1) * 2;
                    MMA16816(acc[mt][nt], afh[mt][0], afh[mt][1], afh[mt][2], afh[mt][3],
                             bfh[p][q], bfh[p][q + 1]);
                    MMA16816(acc[mt][nt], afh[mt][0], afh[mt][1], afh[mt][2], afh[mt][3],
                             bfl[p][q], bfl[p][q + 1]);
                    MMA16816(acc[mt][nt], afl[mt][0], afl[mt][1], afl[mt][2], afl[mt][3],
                             bfh[p][q], bfh[p][q + 1]);
                }
        }
        __syncthreads();
    }

    const int erow = lane >> 2;
    const int ecol = 2 * (lane & 3);
#pragma unroll
    for (int mt = 0; mt < 2; mt++)
#pragma unroll
        for (int nt = 0; nt < 4; nt++) {
            int row0 = bm + wm + mt * 16 + erow;
            int col  = bn + wn + nt * 8 + ecol;
            float b0 = bias[col], b1 = bias[col + 1];
            float v00 = acc[mt][nt][0] + b0, v01 = acc[mt][nt][1] + b1;
            float v10 = acc[mt][nt][2] + b0, v11 = acc[mt][nt][3] + b1;
            if (EPI == 1) {
                v00 = 0.5f * v00 * (1.0f + erff(v00 * 0.70710678118654752f));
                v01 = 0.5f * v01 * (1.0f + erff(v01 * 0.70710678118654752f));
                v10 = 0.5f * v10 * (1.0f + erff(v10 * 0.70710678118654752f));
                v11 = 0.5f * v11 * (1.0f + erff(v11 * 0.70710678118654752f));
                __nv_bfloat16 h0, l0, h1, l1;
                split2(v00, h0, l0); split2(v01, h1, l1);
                *(__nv_bfloat162*)(Oh + (size_t)row0 * N + col) = __nv_bfloat162(h0, h1);
                *(__nv_bfloat162*)(Ol + (size_t)row0 * N + col) = __nv_bfloat162(l0, l1);
                split2(v10, h0, l0); split2(v11, h1, l1);
                *(__nv_bfloat162*)(Oh + (size_t)(row0 + 8) * N + col) = __nv_bfloat162(h0, h1);
                *(__nv_bfloat162*)(Ol + (size_t)(row0 + 8) * N + col) = __nv_bfloat162(l0, l1);
            } else {
                float2* p0 = (float2*)(C + (size_t)row0 * N + col);
                float2* p1 = (float2*)(C + (size_t)(row0 + 8) * N + col);
                if (EPI == 2) {
                    float2 c0 = *p0, c1 = *p1;
                    v00 += c0.x; v01 += c0.y; v10 += c1.x; v11 += c1.y;
                }
                *p0 = make_float2(v00, v01);
                *p1 = make_float2(v10, v11);
            }
        }
}

// ---------------------------------------------------------------------------
// HMMA flash attention + fused residual add (bf16x3 split, fp32 softmax).
// Grid (qtile=8, head=12, batch=16), 128 threads = 4 warps, warp = 16 q-rows.
// smem (halves): Qh@0 Ql@4608 Kh@9216 Kl@13824 Vh@18432(T) Vl@23040(T), row 72.
// ---------------------------------------------------------------------------
#define AQH 0
#define AQL 4608
#define AKH 9216
#define AKL 13824
#define AVH 18432
#define AVL 23040
#define ATT_SMEM (6 * 4608 * 2)   // 55296 B

__global__ __launch_bounds__(128) void attn_hmma(
    const float* __restrict__ Qg, const float* __restrict__ Kg,
    const float* __restrict__ Vg, float* __restrict__ X)
{
    extern __shared__ __nv_bfloat16 sh[];
    const int tid = threadIdx.x;
    const int warp = tid >> 5, lane = tid & 31;
    const int qt = blockIdx.x, h = blockIdx.y, b = blockIdx.z;
    const int q0 = b * SEQ + qt * 64;
    const int hc = h * HDIMV;
    const uint32_t base = (uint32_t)__cvta_generic_to_shared(sh);

    const int lrow = tid >> 1, ldb = (tid & 1) * 32;   // load: 2 thr/row, 32 f each

    // ---- load Q tile (64 x 64), split ----
    {
        const float* src = Qg + (size_t)(q0 + lrow) * DIMV + hc + ldb;
#pragma unroll
        for (int j = 0; j < 8; j++) {
            float4 v = *(const float4*)(src + j * 4);
            __nv_bfloat16 hh0, ll0;
            int o = lrow * 72 + ldb + j * 4;
            split2(v.x, hh0, ll0); sh[AQH + o + 0] = hh0; sh[AQL + o + 0] = ll0;
            split2(v.y, hh0, ll0); sh[AQH + o + 1] = hh0; sh[AQL + o + 1] = ll0;
            split2(v.z, hh0, ll0); sh[AQH + o + 2] = hh0; sh[AQL + o + 2] = ll0;
            split2(v.w, hh0, ll0); sh[AQH + o + 3] = hh0; sh[AQL + o + 3] = ll0;
        }
    }
    __syncthreads();

    // ---- preload Q hi fragments (lo reloaded per kk to save regs) ----
    const int wm = warp * 16;
    const uint32_t a_row = wm + (lane & 15);
    const uint32_t a_koff = ((lane >> 4) & 1) * 8;
    uint32_t qfh[4][4];
#pragma unroll
    for (int t = 0; t < 4; t++) {
        uint32_t adr = base + (AQH + a_row * 72 + t * 16 + a_koff) * 2;
        LDM_X4(qfh[t][0], qfh[t][1], qfh[t][2], qfh[t][3], adr);
    }
    const uint32_t b_row = (lane & 7) + ((lane >> 4) & 1) * 8;
    const uint32_t b_koff = ((lane >> 3) & 1) * 8;

    float o[8][4];
#pragma unroll
    for (int dt = 0; dt < 8; dt++)
#pragma unroll
        for (int i = 0; i < 4; i++) o[dt][i] = 0.f;
    float m0 = -1e30f, m1 = -1e30f, l0 = 0.f, l1 = 0.f;

    for (int kt = 0; kt < 8; kt++) {
        const int k0 = b * SEQ + kt * 64;
        // ---- load K (natural) and V (transposed [d][key]), split ----
        {
            const float* ks = Kg + (size_t)(k0 + lrow) * DIMV + hc + ldb;
            const float* vs = Vg + (size_t)(k0 + lrow) * DIMV + hc + ldb;
#pragma unroll
            for (int j = 0; j < 8; j++) {
                float4 kv = *(const float4*)(ks + j * 4);
                float4 vv = *(const float4*)(vs + j * 4);
                __nv_bfloat16 hh0, ll0;
                int ko = lrow * 72 + ldb + j * 4;
                split2(kv.x, hh0, ll0); sh[AKH + ko + 0] = hh0; sh[AKL + ko + 0] = ll0;
                split2(kv.y, hh0, ll0); sh[AKH + ko + 1] = hh0; sh[AKL + ko + 1] = ll0;
                split2(kv.z, hh0, ll0); sh[AKH + ko + 2] = hh0; sh[AKL + ko + 2] = ll0;
                split2(kv.w, hh0, ll0); sh[AKH + ko + 3] = hh0; sh[AKL + ko + 3] = ll0;
                int d0 = ldb + j * 4;
                split2(vv.x, hh0, ll0); sh[AVH + (d0 + 0) * 72 + lrow] = hh0; sh[AVL + (d0 + 0) * 72 + lrow] = ll0;
                split2(vv.y, hh0, ll0); sh[AVH + (d0 + 1) * 72 + lrow] = hh0; sh[AVL + (d0 + 1) * 72 + lrow] = ll0;
                split2(vv.z, hh0, ll0); sh[AVH + (d0 + 2) * 72 + lrow] = hh0; sh[AVL + (d0 + 2) * 72 + lrow] = ll0;
                split2(vv.w, hh0, ll0); sh[AVH + (d0 + 3) * 72 + lrow] = hh0; sh[AVL + (d0 + 3) * 72 + lrow] = ll0;
            }
        }
        __syncthreads();

        // ---- S = Q K^T (m16 x n64 per warp), bf16x3 ----
        float sf[8][4];
#pragma unroll
        for (int nt = 0; nt < 8; nt++)
#pragma unroll
            for (int i = 0; i < 4; i++) sf[nt][i] = 0.f;

#pragma unroll
        for (int kk = 0; kk < 4; kk++) {
            uint32_t qfl[4];
            uint32_t adr = base + (AQL + a_row * 72 + kk * 16 + a_koff) * 2;
            LDM_X4(qfl[0], qfl[1], qfl[2], qfl[3], adr);
            uint32_t kfh[4][4], kfl[4][4];
#pragma unroll
            for (int g = 0; g < 4; g++) {
                adr = base + (AKH + (g * 16 + b_row) * 72 + kk * 16 + b_koff) * 2;
                LDM_X4(kfh[g][0], kfh[g][1], kfh[g][2], kfh[g][3], adr);
                adr = base + (AKL + (g * 16 + b_row) * 72 + kk * 16 + b_koff) * 2;
                LDM_X4(kfl[g][0], kfl[g][1], kfl[g][2], kfl[g][3], adr);
            }
#pragma unroll
            for (int nt = 0; nt < 8; nt++) {
                const int g = nt >> 1, q = (nt & 1) * 2;
                MMA16816(sf[nt], qfh[kk][0], qfh[kk][1], qfh[kk][2], qfh[kk][3],
                         kfh[g][q], kfh[g][q + 1]);
                MMA16816(sf[nt], qfh[kk][0], qfh[kk][1], qfh[kk][2], qfh[kk][3],
                         kfl[g][q], kfl[g][q + 1]);
                MMA16816(sf[nt], qfl[0], qfl[1], qfl[2], qfl[3],
                         kfh[g][q], kfh[g][q + 1]);
            }
        }

        // ---- online softmax (rows erow, erow+8; 4 lanes share a row) ----
        float mt0 = -1e30f, mt1 = -1e30f;
#pragma unroll
        for (int nt = 0; nt < 8; nt++) {
            sf[nt][0] *= 0.125f; sf[nt][1] *= 0.125f;
            sf[nt][2] *= 0.125f; sf[nt][3] *= 0.125f;
            mt0 = fmaxf(mt0, fmaxf(sf[nt][0], sf[nt][1]));
            mt1 = fmaxf(mt1, fmaxf(sf[nt][2], sf[nt][3]));
        }
        mt0 = fmaxf(mt0, __shfl_xor_sync(0xffffffffu, mt0, 1));
        mt0 = fmaxf(mt0, __shfl_xor_sync(0xffffffffu, mt0, 2));
        mt1 = fmaxf(mt1, __shfl_xor_sync(0xffffffffu, mt1, 1));
        mt1 = fmaxf(mt1, __shfl_xor_sync(0xffffffffu, mt1, 2));
        float mn0 = fmaxf(m0, mt0), mn1 = fmaxf(m1, mt1);
        float al0 = __expf(m0 - mn0), al1 = __expf(m1 - mn1);
        float rs0 = 0.f, rs1 = 0.f;
#pragma unroll
        for (int nt = 0; nt < 8; nt++) {
            sf[nt][0] = __expf(sf[nt][0] - mn0);
            sf[nt][1] = __expf(sf[nt][1] - mn0);
            sf[nt][2] = __expf(sf[nt][2] - mn1);
            sf[nt][3] = __expf(sf[nt][3] - mn1);
            rs0 += sf[nt][0] + sf[nt][1];
            rs1 += sf[nt][2] + sf[nt][3];
        }
        rs0 += __shfl_xor_sync(0xffffffffu, rs0, 1);
        rs0 += __shfl_xor_sync(0xffffffffu, rs0, 2);
        rs1 += __shfl_xor_sync(0xffffffffu, rs1, 1);
        rs1 += __shfl_xor_sync(0xffffffffu, rs1, 2);
        l0 = l0 * al0 + rs0; m0 = mn0;
        l1 = l1 * al1 + rs1; m1 = mn1;
#pragma unroll
        for (int dt = 0; dt < 8; dt++) {
            o[dt][0] *= al0; o[dt][1] *= al0;
            o[dt][2] *= al1; o[dt][3] *= al1;
        }

        // ---- pack P (C-frag -> A-frag, in registers) with hi/lo split ----
        uint32_t pah[4][4], pal[4][4];
#pragma unroll
        for (int t2 = 0; t2 < 4; t2++) {
            pack_split(sf[2 * t2][0],     sf[2 * t2][1],     pah[t2][0], pal[t2][0]);
            pack_split(sf[2 * t2][2],     sf[2 * t2][3],     pah[t2][1], pal[t2][1]);
            pack_split(sf[2 * t2 + 1][0], sf[2 * t2 + 1][1], pah[t2][2], pal[t2][2]);
            pack_split(sf[2 * t2 + 1][2], sf[2 * t2 + 1][3], pah[t2][3], pal[t2][3]);
        }

        // ---- O += P V  (V smem is [d][key], same B pattern as GEMM) ----
#pragma unroll
        for (int t2 = 0; t2 < 4; t2++) {
            uint32_t vfh[4][4], vfl[4][4];
#pragma unroll
            for (int g = 0; g < 4; g++) {
                uint32_t adr = base + (AVH + (g * 16 + b_row) * 72 + t2 * 16 + b_koff) * 2;
                LDM_X4(vfh[g][0], vfh[g][1], vfh[g][2], vfh[g][3], adr);
                adr = base + (AVL + (g * 16 + b_row) * 72 + t2 * 16 + b_koff) * 2;
                LDM_X4(vfl[g][0], vfl[g][1], vfl[g][2], vfl[g][3], adr);
            }
#pragma unroll
            for (int dt = 0; dt < 8; dt++) {
                const int g = dt >> 1, q = (dt & 1) * 2;
                MMA16816(o[dt], pah[t2][0], pah[t2][1], pah[t2][2], pah[t2][3],
                         vfh[g][q], vfh[g][q + 1]);
                MMA16816(o[dt], pal[t2][0], pal[t2][1], pal[t2][2], pal[t2][3],
                         vfh[g][q], vfh[g][q + 1]);
                MMA16816(o[dt], pah[t2][0], pah[t2][1], pah[t2][2], pah[t2][3],
                         vfl[g][q], vfl[g][q + 1]);
            }
        }
        __syncthreads();
    }

    // ---- write: X += O / l  (disjoint columns per head) ----
    const float i0 = 1.f / l0, i1 = 1.f / l1;
    const int erow = lane >> 2, ecol = 2 * (lane & 3);
    const int row0 = q0 + wm + erow;
#pragma unroll
    for (int dt = 0; dt < 8; dt++) {
        int col = hc + dt * 8 + ecol;
        float2* p0 = (float2*)(X + (size_t)row0 * DIMV + col);
        float2* p1 = (float2*)(X + (size_t)(row0 + 8) * DIMV + col);
        float2 c0 = *p0, c1 = *p1;
        c0.x += o[dt][0] * i0; c0.y += o[dt][1] * i0;
        c1.x += o[dt][2] * i1; c1.y += o[dt][3] * i1;
        *p0 = c0; *p1 = c1;
    }
}

// ---------------------------------------------------------------------------
// Launch
// ---------------------------------------------------------------------------
extern "C" void kernel_launch(void* const* d_in, const int* in_sizes, int n_in,
                              void* d_out, int out_size)
{
    const float* x_in = (const float*)d_in[0];
    const float* ln_w = (const float*)d_in[1];
    const float* ln_b = (const float*)d_in[2];
    const float* wq   = (const float*)d_in[3];
    const float* bq   = (const float*)d_in[4];
    const float* wk   = (const float*)d_in[5];
    const float* bk   = (const float*)d_in[6];
    const float* wv   = (const float*)d_in[7];
    const float* bv   = (const float*)d_in[8];
    const float* w1   = (const float*)d_in[9];
    const float* b1   = (const float*)d_in[10];
    const float* w2   = (const float*)d_in[11];
    const float* b2   = (const float*)d_in[12];

    float* X = (float*)d_out;

    __nv_bfloat16 *lnh, *lnl, *hh, *hl;
    __nv_bfloat16 *wqh, *wql, *wkh, *wkl, *wvh, *wvl, *w1h, *w1l, *w2h, *w2l;
    float *q, *k, *v;
    cudaGetSymbolAddress((void**)&lnh, g_lnh);
    cudaGetSymbolAddress((void**)&lnl, g_lnl);
    cudaGetSymbolAddress((void**)&hh,  g_hh);
    cudaGetSymbolAddress((void**)&hl,  g_hl);
    cudaGetSymbolAddress((void**)&q,   g_q);
    cudaGetSymbolAddress((void**)&k,   g_k);
    cudaGetSymbolAddress((void**)&v,   g_v);
    cudaGetSymbolAddress((void**)&wqh, g_wqh);
    cudaGetSymbolAddress((void**)&wql, g_wql);
    cudaGetSymbolAddress((void**)&wkh, g_wkh);
    cudaGetSymbolAddress((void**)&wkl, g_wkl);
    cudaGetSymbolAddress((void**)&wvh, g_wvh);
    cudaGetSymbolAddress((void**)&wvl, g_wvl);
    cudaGetSymbolAddress((void**)&w1h, g_w1h);
    cudaGetSymbolAddress((void**)&w1l, g_w1l);
    cudaGetSymbolAddress((void**)&w2h, g_w2h);
    cudaGetSymbolAddress((void**)&w2l, g_w2l);

    cudaFuncSetAttribute(gemm_hmma<0>, cudaFuncAttributeMaxDynamicSharedMemorySize, GEMM_SMEM);
    cudaFuncSetAttribute(gemm_hmma<1>, cudaFuncAttributeMaxDynamicSharedMemorySize, GEMM_SMEM);
    cudaFuncSetAttribute(gemm_hmma<2>, cudaFuncAttributeMaxDynamicSharedMemorySize, GEMM_SMEM);
    cudaFuncSetAttribute(attn_hmma,    cudaFuncAttributeMaxDynamicSharedMemorySize, ATT_SMEM);

    // residual stream <- input
    cudaMemcpyAsync(X, x_in, sizeof(float) * (size_t)MROWS * DIMV,
                    cudaMemcpyDeviceToDevice, 0);

    // fused weight prep (single launch)
    wprep_all<<<dim3(96, 96, 5), dim3(32, 8)>>>(wq, wk, wv, w1, w2,
        wqh, wql, wkh, wkl, wvh, wvl, w1h, w1l, w2h, w2l);

    dim3 gQKV(DIMV / 64, MROWS / 128);    // (12, 64)
    dim3 gMLP1(MLPD / 64, MROWS / 128);   // (48, 64)
    dim3 gAttn(SEQ / 64, NHEAD, BATCH);   // (8, 12, 16)

    for (int layer = 0; layer < DEPTH; layer++) {
        ln_split_kernel<<<MROWS, 256>>>(X, ln_w, ln_b, lnh, lnl);

        gemm_hmma<0><<<gQKV, 256, GEMM_SMEM>>>(lnh, lnl, wqh, wql, bq, q, nullptr, nullptr, DIMV, DIMV);
        gemm_hmma<0><<<gQKV, 256, GEMM_SMEM>>>(lnh, lnl, wkh, wkl, bk, k, nullptr, nullptr, DIMV, DIMV);
        gemm_hmma<0><<<gQKV, 256, GEMM_SMEM>>>(lnh, lnl, wvh, wvl, bv, v, nullptr, nullptr, DIMV, DIMV);

        attn_hmma<<<gAttn, 128, ATT_SMEM>>>(q, k, v, X);

        ln_split_kernel<<<MROWS, 256>>>(X, ln_w, ln_b, lnh, lnl);

        gemm_hmma<1><<<gMLP1, 256, GEMM_SMEM>>>(lnh, lnl, w1h, w1l, b1, nullptr, hh, hl, MLPD, DIMV);
        gemm_hmma<2><<<gQKV, 256, GEMM_SMEM>>>(hh, hl, w2h, w2l, b2, X, nullptr, nullptr, DIMV, MLPD);
    }
}